// round 3
// baseline (speedup 1.0000x reference)
#include <cuda_runtime.h>

// CRF NLL: B=1024, T=512, K=64, START=62, STOP=63
// Exp-domain forward recursion, ONE WARP per batch element (no __syncthreads).
// Thread i owns output rows 2i, 2i+1. v[64] in shared, __syncwarp per step.
//   v[j] = exp(alpha[j] - ktot*ln2);  v' = (Et @ v) .* exp(emit) .* 2^-k
// Et = exp(trans), two rows register-resident per thread as f32x2 pairs.
// Emissions prefetched 8 steps ahead and exp'd one 4-step group ahead.

#define B_ 1024
#define T_ 512
#define K_ 64
#define START_ 62
#define STOP_ 63

typedef unsigned long long u64;

__device__ __forceinline__ u64 fma2(u64 a, u64 b, u64 c) {
    u64 d;
    asm("fma.rn.f32x2 %0, %1, %2, %3;" : "=l"(d) : "l"(a), "l"(b), "l"(c));
    return d;
}
__device__ __forceinline__ u64 add2(u64 a, u64 b) {
    u64 d;
    asm("add.rn.f32x2 %0, %1, %2;" : "=l"(d) : "l"(a), "l"(b));
    return d;
}
__device__ __forceinline__ u64 pack2(float lo, float hi) {
    u64 d;
    asm("mov.b64 %0, {%1, %2};" : "=l"(d) : "f"(lo), "f"(hi));
    return d;
}
__device__ __forceinline__ float sum2(u64 a) {
    float lo, hi;
    asm("mov.b64 {%0, %1}, %2;" : "=f"(lo), "=f"(hi) : "l"(a));
    return lo + hi;
}
// max of the two packed floats (all v >= 0)
__device__ __forceinline__ float pmax2(u64 a) {
    float lo, hi;
    asm("mov.b64 {%0, %1}, %2;" : "=f"(lo), "=f"(hi) : "l"(a));
    return fmaxf(lo, hi);
}

__global__ void crf_zero_kernel(float* out) { out[0] = 0.0f; }

__global__ __launch_bounds__(32) void crf_fwd_kernel(
    const float* __restrict__ feats,      // [B,T,K]
    const int*   __restrict__ lengths,    // [B]
    const int*   __restrict__ tags,       // [B,T]
    const float* __restrict__ trans,      // [K,K] trans[next, prev]
    float* __restrict__ out)
{
    __shared__ __align__(16) float vbuf[2][64];

    const int i = threadIdx.x;            // owns rows 2i, 2i+1
    const int b = blockIdx.x;
    const int len = lengths[b];

    const float* fb = feats + (size_t)b * (T_ * K_);
    const int*   tb = tags  + (size_t)b * T_;

    // ---- gold score, fully parallel over t ----
    float gold = 0.0f;
#pragma unroll
    for (int r = 0; r < 16; ++r) {
        int t = i + 32 * r;
        if (t < len) {
            int tg = tb[t];
            int pv = t ? tb[t - 1] : START_;
            gold += fb[t * K_ + tg] + trans[tg * K_ + pv];
        }
    }
    if (i == 0) gold += trans[STOP_ * K_ + tb[len - 1]];

    // ---- Et rows 2i and 2i+1, f32x2-packed over j ----
    u64 EtA[32], EtB[32];
#pragma unroll
    for (int q = 0; q < 32; ++q) {
        EtA[q] = pack2(__expf(trans[(2 * i)     * K_ + 2 * q]),
                       __expf(trans[(2 * i)     * K_ + 2 * q + 1]));
        EtB[q] = pack2(__expf(trans[(2 * i + 1) * K_ + 2 * q]),
                       __expf(trans[(2 * i + 1) * K_ + 2 * q + 1]));
    }
    const float EtS0 = __expf(trans[STOP_ * K_ + 2 * i]);
    const float EtS1 = __expf(trans[STOP_ * K_ + 2 * i + 1]);

    // v0: 1 at START, 0 elsewhere
    {
        float2 v0;
        v0.x = (2 * i     == START_) ? 1.0f : 0.0f;
        v0.y = (2 * i + 1 == START_) ? 1.0f : 0.0f;
        ((float2*)vbuf[0])[i] = v0;
    }

    // ---- emission prefetch: float2 (rows 2i,2i+1) per step, 4-step groups ----
    const float2* fb2 = (const float2*)fb;     // [T][32] float2
    float2 c0 = fb2[0 * 32 + i], c1 = fb2[1 * 32 + i],
           c2 = fb2[2 * 32 + i], c3 = fb2[3 * 32 + i];
    float2 n0 = fb2[4 * 32 + i], n1 = fb2[5 * 32 + i],
           n2 = fb2[6 * 32 + i], n3 = fb2[7 * 32 + i];
    // exp'd current group (off the critical chain)
    float2 ce0 = make_float2(__expf(c0.x), __expf(c0.y));
    float2 ce1 = make_float2(__expf(c1.x), __expf(c1.y));
    float2 ce2 = make_float2(__expf(c2.x), __expf(c2.y));
    float2 ce3 = make_float2(__expf(c3.x), __expf(c3.y));
    __syncwarp();

    int ktot = 0, cur = 0;
    const int len4 = len & ~3;

#define STEP(CE)                                                           \
    {                                                                      \
        const ulonglong2* vv = (const ulonglong2*)vbuf[cur];               \
        u64 a0 = 0ull, a1 = 0ull, b0 = 0ull, b1 = 0ull;                    \
        _Pragma("unroll")                                                  \
        for (int q = 0; q < 16; ++q) {                                     \
            ulonglong2 x = vv[q];                                          \
            a0 = fma2(EtA[2 * q],     x.x, a0);                            \
            a1 = fma2(EtA[2 * q + 1], x.y, a1);                            \
            b0 = fma2(EtB[2 * q],     x.x, b0);                            \
            b1 = fma2(EtB[2 * q + 1], x.y, b1);                            \
        }                                                                  \
        float w0 = sum2(add2(a0, a1)) * (CE).x;                            \
        float w1 = sum2(add2(b0, b1)) * (CE).y;                            \
        cur ^= 1;                                                          \
        ((float2*)vbuf[cur])[i] = make_float2(w0, w1);                     \
        __syncwarp();                                                      \
    }

#define STEP_RESCALE(CE)                                                   \
    {                                                                      \
        const ulonglong2* vv = (const ulonglong2*)vbuf[cur];               \
        u64 a0 = 0ull, a1 = 0ull, b0 = 0ull, b1 = 0ull;                    \
        float mx = 0.0f;                                                   \
        _Pragma("unroll")                                                  \
        for (int q = 0; q < 16; ++q) {                                     \
            ulonglong2 x = vv[q];                                          \
            a0 = fma2(EtA[2 * q],     x.x, a0);                            \
            a1 = fma2(EtA[2 * q + 1], x.y, a1);                            \
            b0 = fma2(EtB[2 * q],     x.x, b0);                            \
            b1 = fma2(EtB[2 * q + 1], x.y, b1);                            \
            mx = fmaxf(mx, fmaxf(pmax2(x.x), pmax2(x.y)));                 \
        }                                                                  \
        float w0 = sum2(add2(a0, a1)) * (CE).x;                            \
        float w1 = sum2(add2(b0, b1)) * (CE).y;                            \
        if (mx > 0.0f) {                                                   \
            /* identical mx on every thread (all read all 64 v) */         \
            int k = ((__float_as_int(mx) >> 23) & 0xFF) - 127;             \
            ktot += k;                                                     \
            float sc = __int_as_float((127 - k) << 23);                    \
            w0 *= sc; w1 *= sc;                                            \
        }                                                                  \
        cur ^= 1;                                                          \
        ((float2*)vbuf[cur])[i] = make_float2(w0, w1);                     \
        __syncwarp();                                                      \
    }

    for (int t0 = 0; t0 < len4; t0 += 4) {
        // prefetch group t0+8 and exp the next group while the 4 steps run
        int p = t0 + 8;
        float2 g0, g1, g2, g3;
        if (p < T_) {
            g0 = fb2[(p + 0) * 32 + i];
            g1 = fb2[(p + 1) * 32 + i];
            g2 = fb2[(p + 2) * 32 + i];
            g3 = fb2[(p + 3) * 32 + i];
        } else {
            g0 = g1 = g2 = g3 = make_float2(0.f, 0.f);
        }
        float2 ne0 = make_float2(__expf(n0.x), __expf(n0.y));
        float2 ne1 = make_float2(__expf(n1.x), __expf(n1.y));
        float2 ne2 = make_float2(__expf(n2.x), __expf(n2.y));
        float2 ne3 = make_float2(__expf(n3.x), __expf(n3.y));

        STEP(ce0);
        STEP(ce1);
        STEP(ce2);
        STEP_RESCALE(ce3);

        ce0 = ne0; ce1 = ne1; ce2 = ne2; ce3 = ne3;
        n0 = g0; n1 = g1; n2 = g2; n3 = g3;
    }

    const int rem = len - len4;
    if (rem > 0) STEP(ce0);
    if (rem > 1) STEP(ce1);
    if (rem > 2) STEP(ce2);

#undef STEP
#undef STEP_RESCALE

    // ---- terminal: fwd = ktot*ln2 + log( sum_i v[i]*exp(trans[STOP,i]) ) ----
    float2 vf = ((float2*)vbuf[cur])[i];   // own stores, program-ordered
    float u = vf.x * EtS0 + vf.y * EtS1;
#pragma unroll
    for (int off = 16; off; off >>= 1) {
        u    += __shfl_xor_sync(0xFFFFFFFFu, u,    off);
        gold += __shfl_xor_sync(0xFFFFFFFFu, gold, off);
    }
    if (i == 0) {
        float fwd = (float)((double)ktot * 0.69314718055994530942) + logf(u);
        atomicAdd(out, (fwd - gold) * (1.0f / (float)B_));
    }
}

extern "C" void kernel_launch(void* const* d_in, const int* in_sizes, int n_in,
                              void* d_out, int out_size)
{
    const float* feats   = (const float*)d_in[0];
    const int*   lengths = (const int*)  d_in[1];
    const int*   tags    = (const int*)  d_in[2];
    const float* trans   = (const float*)d_in[3];
    float* out = (float*)d_out;

    crf_zero_kernel<<<1, 1>>>(out);
    crf_fwd_kernel<<<B_, 32>>>(feats, lengths, tags, trans, out);
}

// round 4
// speedup vs baseline: 1.0541x; 1.0541x over previous
#include <cuda_runtime.h>

// CRF NLL: B=1024, T=512, K=64, START=62, STOP=63
// Exp-domain forward recursion, one warp per batch element.
// Thread i owns output rows 2i, 2i+1.
//   v[j] = exp(alpha[j] - ktot*ln2);  v' = (Et @ v) .* exp(emit) .* 2^-k
// Key change vs R3: v preloaded into registers in a separate unrolled loop
// (16 outstanding LDS, latency pipelined) then scalar-FFMA matvec on regs.

#define B_ 1024
#define T_ 512
#define K_ 64
#define START_ 62
#define STOP_ 63

__global__ void crf_zero_kernel(float* out) { out[0] = 0.0f; }

__global__ __launch_bounds__(32) void crf_fwd_kernel(
    const float* __restrict__ feats,      // [B,T,K]
    const int*   __restrict__ lengths,    // [B]
    const int*   __restrict__ tags,       // [B,T]
    const float* __restrict__ trans,      // [K,K] trans[next, prev]
    float* __restrict__ out)
{
    __shared__ __align__(16) float vbuf[2][64];

    const int i = threadIdx.x;            // owns rows 2i, 2i+1
    const int b = blockIdx.x;
    const int len = lengths[b];

    const float* fb = feats + (size_t)b * (T_ * K_);
    const int*   tb = tags  + (size_t)b * T_;

    // ---- gold score, fully parallel over t ----
    float gold = 0.0f;
#pragma unroll
    for (int r = 0; r < 16; ++r) {
        int t = i + 32 * r;
        if (t < len) {
            int tg = tb[t];
            int pv = t ? tb[t - 1] : START_;
            gold += fb[t * K_ + tg] + trans[tg * K_ + pv];
        }
    }
    if (i == 0) gold += trans[STOP_ * K_ + tb[len - 1]];

    // ---- Et rows 2i, 2i+1 register-resident (scalar) ----
    float EtA[64], EtB[64];
#pragma unroll
    for (int j = 0; j < 64; ++j) {
        EtA[j] = __expf(trans[(2 * i)     * K_ + j]);
        EtB[j] = __expf(trans[(2 * i + 1) * K_ + j]);
    }
    const float EtS0 = __expf(trans[STOP_ * K_ + 2 * i]);
    const float EtS1 = __expf(trans[STOP_ * K_ + 2 * i + 1]);

    // v0: 1 at START, 0 elsewhere
    {
        float2 v0;
        v0.x = (2 * i     == START_) ? 1.0f : 0.0f;
        v0.y = (2 * i + 1 == START_) ? 1.0f : 0.0f;
        ((float2*)vbuf[0])[i] = v0;
    }

    // ---- emission prefetch: float2 per step, 4-step groups, 8 ahead ----
    const float2* fb2 = (const float2*)fb;     // [T][32]
    float2 n0 = fb2[4 * 32 + i], n1 = fb2[5 * 32 + i],
           n2 = fb2[6 * 32 + i], n3 = fb2[7 * 32 + i];
    float2 c0 = fb2[0 * 32 + i], c1 = fb2[1 * 32 + i],
           c2 = fb2[2 * 32 + i], c3 = fb2[3 * 32 + i];
    float2 ce0 = make_float2(__expf(c0.x), __expf(c0.y));
    float2 ce1 = make_float2(__expf(c1.x), __expf(c1.y));
    float2 ce2 = make_float2(__expf(c2.x), __expf(c2.y));
    float2 ce3 = make_float2(__expf(c3.x), __expf(c3.y));
    __syncwarp();

    int ktot = 0, cur = 0;
    const int len4 = len & ~3;

    // One step: preload ALL of v into registers first (pipelined LDS),
    // then scalar-FFMA matvec entirely on registers.
#define STEP_BODY(CE, DO_RESCALE)                                          \
    {                                                                      \
        const float4* vv = (const float4*)vbuf[cur];                       \
        float4 x[16];                                                      \
        _Pragma("unroll")                                                  \
        for (int q = 0; q < 16; ++q) x[q] = vv[q];                         \
        float a0 = 0.f, a1 = 0.f, a2 = 0.f, a3 = 0.f;                      \
        float b0 = 0.f, b1 = 0.f, b2 = 0.f, b3 = 0.f;                      \
        _Pragma("unroll")                                                  \
        for (int q = 0; q < 16; ++q) {                                     \
            a0 = fmaf(EtA[4 * q + 0], x[q].x, a0);                         \
            a1 = fmaf(EtA[4 * q + 1], x[q].y, a1);                         \
            a2 = fmaf(EtA[4 * q + 2], x[q].z, a2);                         \
            a3 = fmaf(EtA[4 * q + 3], x[q].w, a3);                         \
            b0 = fmaf(EtB[4 * q + 0], x[q].x, b0);                         \
            b1 = fmaf(EtB[4 * q + 1], x[q].y, b1);                         \
            b2 = fmaf(EtB[4 * q + 2], x[q].z, b2);                         \
            b3 = fmaf(EtB[4 * q + 3], x[q].w, b3);                         \
        }                                                                  \
        float w0 = ((a0 + a1) + (a2 + a3)) * (CE).x;                       \
        float w1 = ((b0 + b1) + (b2 + b3)) * (CE).y;                       \
        if (DO_RESCALE) {                                                  \
            float mx = 0.0f;                                               \
            _Pragma("unroll")                                              \
            for (int q = 0; q < 16; ++q)                                   \
                mx = fmaxf(mx, fmaxf(fmaxf(x[q].x, x[q].y),                \
                                     fmaxf(x[q].z, x[q].w)));              \
            if (mx > 0.0f) {                                               \
                /* identical mx on every thread: all read all 64 v */      \
                int k = ((__float_as_int(mx) >> 23) & 0xFF) - 127;         \
                ktot += k;                                                 \
                float sc = __int_as_float((127 - k) << 23);                \
                w0 *= sc; w1 *= sc;                                        \
            }                                                              \
        }                                                                  \
        cur ^= 1;                                                          \
        ((float2*)vbuf[cur])[i] = make_float2(w0, w1);                     \
        __syncwarp();                                                      \
    }

    for (int t0 = 0; t0 < len4; t0 += 4) {
        // prefetch group t0+8; exp next group (both off the serial chain)
        int p = t0 + 8;
        float2 g0, g1, g2, g3;
        if (p < T_) {
            g0 = fb2[(p + 0) * 32 + i];
            g1 = fb2[(p + 1) * 32 + i];
            g2 = fb2[(p + 2) * 32 + i];
            g3 = fb2[(p + 3) * 32 + i];
        } else {
            g0 = g1 = g2 = g3 = make_float2(0.f, 0.f);
        }
        float2 ne0 = make_float2(__expf(n0.x), __expf(n0.y));
        float2 ne1 = make_float2(__expf(n1.x), __expf(n1.y));
        float2 ne2 = make_float2(__expf(n2.x), __expf(n2.y));
        float2 ne3 = make_float2(__expf(n3.x), __expf(n3.y));

        STEP_BODY(ce0, false);
        STEP_BODY(ce1, false);
        STEP_BODY(ce2, false);
        STEP_BODY(ce3, true);

        ce0 = ne0; ce1 = ne1; ce2 = ne2; ce3 = ne3;
        n0 = g0; n1 = g1; n2 = g2; n3 = g3;
    }

    const int rem = len - len4;
    if (rem > 0) STEP_BODY(ce0, false);
    if (rem > 1) STEP_BODY(ce1, false);
    if (rem > 2) STEP_BODY(ce2, false);

#undef STEP_BODY

    // ---- terminal: fwd = ktot*ln2 + log( sum_i v[i]*exp(trans[STOP,i]) ) ----
    float2 vf = ((float2*)vbuf[cur])[i];   // own stores, program-ordered
    float u = vf.x * EtS0 + vf.y * EtS1;
#pragma unroll
    for (int off = 16; off; off >>= 1) {
        u    += __shfl_xor_sync(0xFFFFFFFFu, u,    off);
        gold += __shfl_xor_sync(0xFFFFFFFFu, gold, off);
    }
    if (i == 0) {
        float fwd = (float)((double)ktot * 0.69314718055994530942) + logf(u);
        atomicAdd(out, (fwd - gold) * (1.0f / (float)B_));
    }
}

extern "C" void kernel_launch(void* const* d_in, const int* in_sizes, int n_in,
                              void* d_out, int out_size)
{
    const float* feats   = (const float*)d_in[0];
    const int*   lengths = (const int*)  d_in[1];
    const int*   tags    = (const int*)  d_in[2];
    const float* trans   = (const float*)d_in[3];
    float* out = (float*)d_out;

    crf_zero_kernel<<<1, 1>>>(out);
    crf_fwd_kernel<<<B_, 32>>>(feats, lengths, tags, trans, out);
}

// round 5
// speedup vs baseline: 1.3466x; 1.2775x over previous
#include <cuda_runtime.h>

// CRF NLL: B=1024, T=512, K=64, START=62, STOP=63
// Exp-domain forward recursion. Persistent kernel: 148 CTAs x 4 warps = 592
// warps (one per SMSP), each warp grabs batches from a global counter in
// descending-length order (LPT). Per step: preload v[64] from shared into
// registers, then 64 x FFMA2 (fma.rn.f32x2) matvec. Et rows are computed
// ONCE per warp and reused across all batches it processes.

#define B_ 1024
#define T_ 512
#define K_ 64
#define START_ 62
#define STOP_ 63

typedef unsigned long long u64;

__device__ int g_order[B_];
__device__ int g_counter;

__device__ __forceinline__ u64 fma2(u64 a, u64 b, u64 c) {
    u64 d;
    asm("fma.rn.f32x2 %0, %1, %2, %3;" : "=l"(d) : "l"(a), "l"(b), "l"(c));
    return d;
}
__device__ __forceinline__ u64 add2(u64 a, u64 b) {
    u64 d;
    asm("add.rn.f32x2 %0, %1, %2;" : "=l"(d) : "l"(a), "l"(b));
    return d;
}
__device__ __forceinline__ u64 pack2(float lo, float hi) {
    u64 d;
    asm("mov.b64 %0, {%1, %2};" : "=l"(d) : "f"(lo), "f"(hi));
    return d;
}
__device__ __forceinline__ float sum2(u64 a) {
    float lo, hi;
    asm("mov.b64 {%0, %1}, %2;" : "=f"(lo), "=f"(hi) : "l"(a));
    return lo + hi;
}
__device__ __forceinline__ float pmax2(u64 a) {   // max of 2 packed floats (>=0)
    float lo, hi;
    asm("mov.b64 {%0, %1}, %2;" : "=f"(lo), "=f"(hi) : "l"(a));
    return fmaxf(lo, hi);
}

// Rank batches by descending length (LPT order), zero accumulator + counter.
__global__ void order_kernel(const int* __restrict__ lengths, float* out) {
    __shared__ int L[B_];
    const int tid = threadIdx.x;                 // 256 threads, grid 4
    for (int j = tid; j < B_; j += 256) L[j] = lengths[j];
    __syncthreads();
    const int b = blockIdx.x * 256 + tid;
    const int mylen = L[b];
    int rank = 0;
    for (int j = 0; j < B_; ++j) {
        int lj = L[j];
        rank += (lj > mylen) || (lj == mylen && j < b);
    }
    g_order[rank] = b;
    if (b == 0) { out[0] = 0.0f; g_counter = 0; }
}

__global__ void __launch_bounds__(128, 1) crf_persistent(
    const float* __restrict__ feats,      // [B,T,K]
    const int*   __restrict__ lengths,    // [B]
    const int*   __restrict__ tags,       // [B,T]
    const float* __restrict__ trans,      // [K,K] trans[next, prev]
    float* __restrict__ out)
{
    __shared__ __align__(16) float vbuf[4][2][64];

    const int lane = threadIdx.x & 31;    // owns rows 2*lane, 2*lane+1
    const int w    = threadIdx.x >> 5;
    float (*vb)[64] = vbuf[w];

    // ---- Et rows for this thread: computed ONCE, reused for all batches ----
    u64 EtA2[32], EtB2[32];
#pragma unroll
    for (int q = 0; q < 32; ++q) {
        EtA2[q] = pack2(__expf(trans[(2 * lane)     * K_ + 2 * q]),
                        __expf(trans[(2 * lane)     * K_ + 2 * q + 1]));
        EtB2[q] = pack2(__expf(trans[(2 * lane + 1) * K_ + 2 * q]),
                        __expf(trans[(2 * lane + 1) * K_ + 2 * q + 1]));
    }
    const float EtS0 = __expf(trans[STOP_ * K_ + 2 * lane]);
    const float EtS1 = __expf(trans[STOP_ * K_ + 2 * lane + 1]);

    for (;;) {
        // ---- grab next batch (longest remaining first) ----
        int r = 0;
        if (lane == 0) r = atomicAdd(&g_counter, 1);
        r = __shfl_sync(0xFFFFFFFFu, r, 0);
        if (r >= B_) break;
        const int b   = g_order[r];
        const int len = lengths[b];

        const float*  fb  = feats + (size_t)b * (T_ * K_);
        const float2* fb2 = (const float2*)fb;          // [T][32]
        const int*    tb  = tags + (size_t)b * T_;

        // ---- gold score, parallel over t ----
        float gold = 0.0f;
#pragma unroll
        for (int q = 0; q < 16; ++q) {
            int t = lane + 32 * q;
            if (t < len) {
                int tg = tb[t];
                int pv = t ? tb[t - 1] : START_;
                gold += fb[t * K_ + tg] + trans[tg * K_ + pv];
            }
        }
        if (lane == 0) gold += trans[STOP_ * K_ + tb[len - 1]];

        // ---- v0 ----
        {
            float2 v0;
            v0.x = (2 * lane     == START_) ? 1.0f : 0.0f;
            v0.y = (2 * lane + 1 == START_) ? 1.0f : 0.0f;
            ((float2*)vb[0])[lane] = v0;
        }

        // ---- emission ring: 4-step groups, 8 ahead, exp'd 1 group ahead ----
        float2 n0 = fb2[4 * 32 + lane], n1 = fb2[5 * 32 + lane],
               n2 = fb2[6 * 32 + lane], n3 = fb2[7 * 32 + lane];
        float2 c0 = fb2[0 * 32 + lane], c1 = fb2[1 * 32 + lane],
               c2 = fb2[2 * 32 + lane], c3 = fb2[3 * 32 + lane];
        float2 ce0 = make_float2(__expf(c0.x), __expf(c0.y));
        float2 ce1 = make_float2(__expf(c1.x), __expf(c1.y));
        float2 ce2 = make_float2(__expf(c2.x), __expf(c2.y));
        float2 ce3 = make_float2(__expf(c3.x), __expf(c3.y));
        __syncwarp();

        int ktot = 0, cur = 0;
        const int len4 = len & ~3;

        // One step: preload v into regs (two halves of 8 LDS.128), then
        // packed-f32x2 matvec on registers only.
#define STEP(CE, DO_RESCALE)                                               \
    {                                                                      \
        const ulonglong2* vv = (const ulonglong2*)vb[cur];                 \
        u64 a0 = 0ull, a1 = 0ull, b0 = 0ull, b1 = 0ull;                    \
        float mx = 0.0f;                                                   \
        _Pragma("unroll")                                                  \
        for (int h = 0; h < 2; ++h) {                                      \
            ulonglong2 x[8];                                               \
            _Pragma("unroll")                                              \
            for (int q = 0; q < 8; ++q) x[q] = vv[8 * h + q];              \
            _Pragma("unroll")                                              \
            for (int q = 0; q < 8; ++q) {                                  \
                a0 = fma2(EtA2[16 * h + 2 * q],     x[q].x, a0);           \
                a1 = fma2(EtA2[16 * h + 2 * q + 1], x[q].y, a1);           \
                b0 = fma2(EtB2[16 * h + 2 * q],     x[q].x, b0);           \
                b1 = fma2(EtB2[16 * h + 2 * q + 1], x[q].y, b1);           \
            }                                                              \
            if (DO_RESCALE) {                                              \
                _Pragma("unroll")                                          \
                for (int q = 0; q < 8; ++q)                                \
                    mx = fmaxf(mx, fmaxf(pmax2(x[q].x), pmax2(x[q].y)));   \
            }                                                              \
        }                                                                  \
        float w0 = sum2(add2(a0, a1)) * (CE).x;                            \
        float w1 = sum2(add2(b0, b1)) * (CE).y;                            \
        if (DO_RESCALE) {                                                  \
            if (mx > 0.0f) {                                               \
                /* identical mx on all threads (all read all 64 v) */      \
                int k = ((__float_as_int(mx) >> 23) & 0xFF) - 127;         \
                ktot += k;                                                 \
                float sc = __int_as_float((127 - k) << 23);                \
                w0 *= sc; w1 *= sc;                                        \
            }                                                              \
        }                                                                  \
        cur ^= 1;                                                          \
        ((float2*)vb[cur])[lane] = make_float2(w0, w1);                    \
        __syncwarp();                                                      \
    }

        for (int t0 = 0; t0 < len4; t0 += 4) {
            int p = t0 + 8;
            float2 g0, g1, g2, g3;
            if (p < T_) {
                g0 = fb2[(p + 0) * 32 + lane];
                g1 = fb2[(p + 1) * 32 + lane];
                g2 = fb2[(p + 2) * 32 + lane];
                g3 = fb2[(p + 3) * 32 + lane];
            } else {
                g0 = g1 = g2 = g3 = make_float2(0.f, 0.f);
            }
            float2 ne0 = make_float2(__expf(n0.x), __expf(n0.y));
            float2 ne1 = make_float2(__expf(n1.x), __expf(n1.y));
            float2 ne2 = make_float2(__expf(n2.x), __expf(n2.y));
            float2 ne3 = make_float2(__expf(n3.x), __expf(n3.y));

            STEP(ce0, false);
            STEP(ce1, false);
            STEP(ce2, false);
            STEP(ce3, true);

            ce0 = ne0; ce1 = ne1; ce2 = ne2; ce3 = ne3;
            n0 = g0; n1 = g1; n2 = g2; n3 = g3;
        }

        const int rem = len - len4;
        if (rem > 0) STEP(ce0, false);
        if (rem > 1) STEP(ce1, false);
        if (rem > 2) STEP(ce2, false);
#undef STEP

        // ---- terminal: fwd = ktot*ln2 + log(sum_i v[i]*exp(trans[STOP,i])) --
        float2 vf = ((float2*)vb[cur])[lane];   // own stores, program-ordered
        float u = vf.x * EtS0 + vf.y * EtS1;
#pragma unroll
        for (int off = 16; off; off >>= 1) {
            u    += __shfl_xor_sync(0xFFFFFFFFu, u,    off);
            gold += __shfl_xor_sync(0xFFFFFFFFu, gold, off);
        }
        if (lane == 0) {
            float fwd = (float)((double)ktot * 0.69314718055994530942)
                      + logf(u);
            atomicAdd(out, (fwd - gold) * (1.0f / (float)B_));
        }
        __syncwarp();
    }
}

extern "C" void kernel_launch(void* const* d_in, const int* in_sizes, int n_in,
                              void* d_out, int out_size)
{
    const float* feats   = (const float*)d_in[0];
    const int*   lengths = (const int*)  d_in[1];
    const int*   tags    = (const int*)  d_in[2];
    const float* trans   = (const float*)d_in[3];
    float* out = (float*)d_out;

    order_kernel<<<4, 256>>>(lengths, out);
    crf_persistent<<<148, 128>>>(feats, lengths, tags, trans, out);
}